// round 2
// baseline (speedup 1.0000x reference)
#include <cuda_runtime.h>
#include <cuda_bf16.h>
#include <cstdint>

// Problem: b=4, h=8, L=8192, dk=dv=64, chunk=32.
// BH = 32 chains, 256 chunks each, G = 8192 total chunks.
#define G_CHUNKS 8192
#define O_ELEMS  16777216   // 4*8*8192*64

// ------------- scratch: __device__ globals (allocation-free rule) ----------
// float4 arrays guarantee 16B alignment for vector LDG.
__device__ float4 g_qn4[G_CHUNKS * 512];   // qn  [g][32][64] row-major
__device__ float4 g_kn4[G_CHUNKS * 512];   // kn  [g][32][64] row-major
__device__ float4 g_w4 [G_CHUNKS * 512];   // w   [g][32][64] row-major
__device__ float4 g_uT4[G_CHUNKS * 512];   // u^T [g][64][32]  (dv-major)
__device__ float4 g_Lc4[G_CHUNKS * 256];   // Lc  [g][32][32] row-major (tril incl diag)

// ===========================================================================
// Phase 1: per-chunk preprocessing. One 256-thread block per chunk.
// ===========================================================================
__global__ void __launch_bounds__(256) dn_phase1(
    const float* __restrict__ q, const float* __restrict__ k,
    const float* __restrict__ v, const float* __restrict__ beta)
{
    __shared__ float sQ[32 * 65], sK[32 * 65], sV[32 * 65];
    __shared__ float sA[32 * 33];     // A -> T (strictly lower), beta-folded
    __shared__ float sWT[64 * 33];    // w transposed staging [d][i]
    __shared__ float sRinv[64], sBeta[32];

    float* g_qn = (float*)g_qn4;  float* g_kn = (float*)g_kn4;
    float* g_w  = (float*)g_w4;   float* g_uT = (float*)g_uT4;
    float* g_Lc = (float*)g_Lc4;

    const int tid  = threadIdx.x;
    const int lane = tid & 31;
    const int wp   = tid >> 5;
    const size_t g = blockIdx.x;

    // ---- load q,k,v chunk (32x64 each) into stride-65 smem ------------------
    const float4* qb = (const float4*)(q + g * 2048);
    const float4* kb = (const float4*)(k + g * 2048);
    const float4* vb = (const float4*)(v + g * 2048);
#pragma unroll
    for (int it = 0; it < 2; ++it) {
        int f  = tid + it * 256;                 // float4 index 0..511
        int so = (f >> 4) * 65 + ((f & 15) << 2);
        float4 a;
        a = qb[f]; sQ[so] = a.x; sQ[so + 1] = a.y; sQ[so + 2] = a.z; sQ[so + 3] = a.w;
        a = kb[f]; sK[so] = a.x; sK[so + 1] = a.y; sK[so + 2] = a.z; sK[so + 3] = a.w;
        a = vb[f]; sV[so] = a.x; sV[so + 1] = a.y; sV[so + 2] = a.z; sV[so + 3] = a.w;
    }
    if (tid < 32) sBeta[tid] = beta[g * 32 + tid];
    __syncthreads();

    // ---- l2-norm rsqrt factors ----------------------------------------------
    if (tid < 64) {
        const float* rp = (tid < 32) ? (sQ + tid * 65) : (sK + (tid - 32) * 65);
        float s = 1e-6f;
#pragma unroll
        for (int d = 0; d < 64; ++d) s = fmaf(rp[d], rp[d], s);
        sRinv[tid] = rsqrtf(s);
    }
    __syncthreads();
    for (int e = tid; e < 2048; e += 256) {
        int r = e >> 6, d = e & 63;
        sQ[r * 65 + d] *= sRinv[r];
        sK[r * 65 + d] *= sRinv[32 + r];
    }
    __syncthreads();

    // ---- A (strict lower, -beta_i * kn_i.kn_j) and Lc = tril(qn kn^T) -------
    {
        const int i0 = wp * 4;
        float accA[4] = {0.f, 0.f, 0.f, 0.f};
        float accL[4] = {0.f, 0.f, 0.f, 0.f};
#pragma unroll 8
        for (int d = 0; d < 64; ++d) {
            float kjd = sK[lane * 65 + d];       // lane = j, conflict-free
#pragma unroll
            for (int e = 0; e < 4; ++e) {
                accA[e] = fmaf(sK[(i0 + e) * 65 + d], kjd, accA[e]);  // broadcast
                accL[e] = fmaf(sQ[(i0 + e) * 65 + d], kjd, accL[e]);  // broadcast
            }
        }
#pragma unroll
        for (int e = 0; e < 4; ++e) {
            int i = i0 + e;
            sA[i * 33 + lane] = (lane < i) ? (-sBeta[i] * accA[e]) : 0.0f;
            g_Lc[g * 1024 + i * 32 + lane] = (lane <= i) ? accL[e] : 0.0f;
        }
    }
    __syncthreads();

    // ---- forward substitution: sA becomes T = (I-A)^{-1} - I (strict lower) -
    if (wp == 0) {
        for (int i = 1; i < 32; ++i) {
            float r   = sA[i * 33 + lane];       // original row i of A
            float val = r;
            for (int j = 1; j < i; ++j) {
                float aij = __shfl_sync(0xffffffffu, r, j);
                if (lane < j) val = fmaf(aij, sA[j * 33 + lane], val);
            }
            sA[i * 33 + lane] = val;
            __syncwarp();
        }
    }
    __syncthreads();

    // ---- fold beta into T columns: T'[i][j] = T[i][j] * beta[j] -------------
    for (int e = tid; e < 1024; e += 256) {
        int i = e >> 5, j = e & 31;
        sA[i * 33 + j] *= sBeta[j];
    }
    __syncthreads();

    // ---- u = M @ (beta*v), w = M @ (beta*kn); M = I + T' (beta-folded) ------
    // u[i][d] = beta_i*v[i][d] + sum_j T'[i][j]*v[j][d]; same for w with kn.
#pragma unroll
    for (int p = 0; p < 4; ++p) {
        int dcb = p * 32 + wp * 4;               // 0..124 step 4
        bool isU = (dcb < 64);
        const float* X = isU ? sV : sK;
        int db = isU ? dcb : (dcb - 64);
        float bi = sBeta[lane];                  // lane = output row i
        float a0 = bi * X[lane * 65 + db + 0];
        float a1 = bi * X[lane * 65 + db + 1];
        float a2 = bi * X[lane * 65 + db + 2];
        float a3 = bi * X[lane * 65 + db + 3];
        for (int j = 0; j < 32; ++j) {
            float t = sA[lane * 33 + j];         // zero for j >= lane
            a0 = fmaf(t, X[j * 65 + db + 0], a0);
            a1 = fmaf(t, X[j * 65 + db + 1], a1);
            a2 = fmaf(t, X[j * 65 + db + 2], a2);
            a3 = fmaf(t, X[j * 65 + db + 3], a3);
        }
        if (isU) {   // store u transposed [d][i] (coalesced: lane = i)
            g_uT[g * 2048 + (size_t)(db + 0) * 32 + lane] = a0;
            g_uT[g * 2048 + (size_t)(db + 1) * 32 + lane] = a1;
            g_uT[g * 2048 + (size_t)(db + 2) * 32 + lane] = a2;
            g_uT[g * 2048 + (size_t)(db + 3) * 32 + lane] = a3;
        } else {
            sWT[(db + 0) * 33 + lane] = a0;
            sWT[(db + 1) * 33 + lane] = a1;
            sWT[(db + 2) * 33 + lane] = a2;
            sWT[(db + 3) * 33 + lane] = a3;
        }
    }
    __syncthreads();

    // ---- store qn, kn, w row-major (coalesced) -------------------------------
    for (int e = tid; e < 2048; e += 256) {
        int r = e >> 6, d = e & 63;
        g_qn[g * 2048 + e] = sQ[r * 65 + d];
        g_kn[g * 2048 + e] = sK[r * 65 + d];
        g_w [g * 2048 + e] = sWT[d * 33 + r];
    }
}

// ===========================================================================
// Phase 2: sequential scan. 128 blocks = 32 bh-chains x 4 dv-splits (16 cols).
// Warp wp owns dv columns c0 = split*16 + wp*2 .. +1. S in regs + smem mirror.
// ===========================================================================

#define LOAD_REGS(T) do {                                                     \
    size_t g_ = gbase + (size_t)(T);                                          \
    const float4* q4_ = (const float4*)((const float*)g_qn4 + g_ * 2048);     \
    const float4* k4_ = (const float4*)((const float*)g_kn4 + g_ * 2048);     \
    const float4* w4_ = (const float4*)((const float*)g_w4  + g_ * 2048);     \
    rq0 = q4_[tid]; rq1 = q4_[tid + 256];                                     \
    rk0 = k4_[tid]; rk1 = k4_[tid + 256];                                     \
    rw0 = w4_[tid]; rw1 = w4_[tid + 256];                                     \
    rl  = ((const float4*)((const float*)g_Lc4 + g_ * 1024))[tid];            \
    ru0 = ((const float*)g_uT4)[g_ * 2048 + (size_t)c0 * 32 + lane];          \
    ru1 = ((const float*)g_uT4)[g_ * 2048 + (size_t)(c0 + 1) * 32 + lane];    \
} while (0)

#define STORE_SMEM() do {                                                     \
    int r0_ = tid >> 4, d0_ = (tid & 15) << 2;                                \
    sQ[r0_*65+d0_]=rq0.x; sQ[r0_*65+d0_+1]=rq0.y; sQ[r0_*65+d0_+2]=rq0.z; sQ[r0_*65+d0_+3]=rq0.w; \
    sK[r0_*65+d0_]=rk0.x; sK[r0_*65+d0_+1]=rk0.y; sK[r0_*65+d0_+2]=rk0.z; sK[r0_*65+d0_+3]=rk0.w; \
    sW[r0_*65+d0_]=rw0.x; sW[r0_*65+d0_+1]=rw0.y; sW[r0_*65+d0_+2]=rw0.z; sW[r0_*65+d0_+3]=rw0.w; \
    int f_ = tid + 256; int r1_ = f_ >> 4, d1_ = (f_ & 15) << 2;              \
    sQ[r1_*65+d1_]=rq1.x; sQ[r1_*65+d1_+1]=rq1.y; sQ[r1_*65+d1_+2]=rq1.z; sQ[r1_*65+d1_+3]=rq1.w; \
    sK[r1_*65+d1_]=rk1.x; sK[r1_*65+d1_+1]=rk1.y; sK[r1_*65+d1_+2]=rk1.z; sK[r1_*65+d1_+3]=rk1.w; \
    sW[r1_*65+d1_]=rw1.x; sW[r1_*65+d1_+1]=rw1.y; sW[r1_*65+d1_+2]=rw1.z; sW[r1_*65+d1_+3]=rw1.w; \
    int lr_ = tid >> 3, lj_ = (tid & 7) << 2;                                 \
    sL[lr_*33+lj_]=rl.x; sL[lr_*33+lj_+1]=rl.y; sL[lr_*33+lj_+2]=rl.z; sL[lr_*33+lj_+3]=rl.w;     \
} while (0)

__global__ void __launch_bounds__(256) dn_phase2(float* __restrict__ out, int wantS)
{
    __shared__ float sQ[32 * 65], sK[32 * 65], sW[32 * 65];
    __shared__ float sL[32 * 33];
    __shared__ float sS[8 * 136];     // per-warp S mirror [d*2 + c], 64x2

    const int tid  = threadIdx.x;
    const int lane = tid & 31;
    const int wp   = tid >> 5;
    const int bh   = blockIdx.x >> 2;
    const int c0   = (blockIdx.x & 3) * 16 + wp * 2;   // global dv col base
    float* mS = sS + wp * 136;

    // init S (regs + mirror)
    *(float2*)(mS + lane * 2)        = make_float2(0.f, 0.f);
    *(float2*)(mS + (lane + 32) * 2) = make_float2(0.f, 0.f);
    float S00 = 0.f, S01 = 0.f, S10 = 0.f, S11 = 0.f;

    const size_t gbase = (size_t)bh * 256;

    float4 rq0, rq1, rk0, rk1, rw0, rw1, rl;
    float ru0, ru1;

    LOAD_REGS(0);
    STORE_SMEM();
    __syncthreads();
    float cu0 = ru0, cu1 = ru1;

    for (int t = 0; t < 256; ++t) {
        if (t + 1 < 256) LOAD_REGS(t + 1);     // prefetch next chunk into regs

        // u = u0 - w@S ; o = q@S  (S = pre-update state, broadcast from mirror)
        float u0 = cu0, u1 = cu1, o0 = 0.f, o1 = 0.f;
#pragma unroll 16
        for (int d = 0; d < 64; ++d) {
            float wv = sW[lane * 65 + d];
            float qv = sQ[lane * 65 + d];
            float2 s = *(const float2*)(mS + d * 2);
            u0 = fmaf(-wv, s.x, u0);  u1 = fmaf(-wv, s.y, u1);
            o0 = fmaf( qv, s.x, o0);  o1 = fmaf( qv, s.y, o1);
        }

        // o += Lc@u (tril mask baked into Lc) ; S += kn^T @ u
#pragma unroll 8
        for (int j = 0; j < 32; ++j) {
            float lc  = sL[lane * 33 + j];      // zero for j > lane
            float uj0 = __shfl_sync(0xffffffffu, u0, j);
            float uj1 = __shfl_sync(0xffffffffu, u1, j);
            o0 = fmaf(lc, uj0, o0);  o1 = fmaf(lc, uj1, o1);
            float ka = sK[j * 65 + lane];
            float kb = sK[j * 65 + lane + 32];
            S00 = fmaf(ka, uj0, S00);  S01 = fmaf(ka, uj1, S01);
            S10 = fmaf(kb, uj0, S10);  S11 = fmaf(kb, uj1, S11);
        }
        __syncwarp();                            // all lanes done reading mS
        *(float2*)(mS + lane * 2)        = make_float2(S00, S01);
        *(float2*)(mS + (lane + 32) * 2) = make_float2(S10, S11);

        size_t orow = ((size_t)bh * 8192 + (size_t)t * 32 + lane) * 64 + c0;
        *(float2*)(out + orow) = make_float2(o0, o1);

        __syncthreads();                         // all warps done with buffers
        if (t + 1 < 256) { STORE_SMEM(); cu0 = ru0; cu1 = ru1; }
        __syncthreads();                         // staged data visible
    }

    if (wantS) {
        size_t sb = (size_t)bh * 4096 + (size_t)lane * 64 + c0;
        out[O_ELEMS + sb]            = S00;
        out[O_ELEMS + sb + 1]        = S01;
        out[O_ELEMS + sb + 2048]     = S10;      // d = lane+32
        out[O_ELEMS + sb + 2048 + 1] = S11;
    }
}

// ===========================================================================
extern "C" void kernel_launch(void* const* d_in, const int* in_sizes, int n_in,
                              void* d_out, int out_size)
{
    const float* q    = (const float*)d_in[0];
    const float* k    = (const float*)d_in[1];
    const float* v    = (const float*)d_in[2];
    const float* beta = (const float*)d_in[3];
    float* out = (float*)d_out;
    int wantS = (out_size > O_ELEMS) ? 1 : 0;

    dn_phase1<<<G_CHUNKS, 256>>>(q, k, v, beta);
    dn_phase2<<<128, 256>>>(out, wantS);
}